// round 9
// baseline (speedup 1.0000x reference)
#include <cuda_runtime.h>
#include <cstdint>

// Perona-Malik single diffusion step — TMA bulk-load staging (8 output rows,
// 10 staged rows = 40KB per block), rolling-register compute from smem,
// direct streaming stores.
// out = clamp(image + g * exp(-g^2/K^2) * dt, 0, 1)
// g   = 5-point Laplacian with ReflectionPad2d(1); K=0.1 (1/K^2=100), dt=0.15

#define W 1024
#define H 1024
#define W4 (W / 4)
#define ROWS 8
#define SROWS (ROWS + 2)

__device__ __forceinline__ void stcs4(float4* p, float4 v) {
    asm volatile("st.global.cs.v4.f32 [%0], {%1,%2,%3,%4};"
                 :: "l"(p), "f"(v.x), "f"(v.y), "f"(v.z), "f"(v.w) : "memory");
}

__global__ __launch_bounds__(256, 5)
void pm_kernel(const float* __restrict__ in, float* __restrict__ out) {
    __shared__ __align__(16) float srows[SROWS][W];   // 40 KB
    __shared__ __align__(8) unsigned long long mbar;

    const int y0 = blockIdx.x * ROWS;      // first output row of this block
    const int n  = blockIdx.y;             // image index
    const int t  = threadIdx.x;            // float4 column 0..255

    const float* img = in  + (size_t)n * (W * H);
    float*       o   = out + (size_t)n * (W * H);

    const uint32_t mbar_addr = (uint32_t)__cvta_generic_to_shared(&mbar);

    if (t == 0) {
        asm volatile("mbarrier.init.shared.b64 [%0], 1;" :: "r"(mbar_addr));
    }
    __syncthreads();

    // Elected thread: expect full 40KB, then issue 10 bulk row copies
    // (global -> smem). Rows reflected at volume edges (-1 -> 1, H -> H-2).
    if (t == 0) {
        asm volatile("mbarrier.arrive.expect_tx.shared.b64 _, [%0], %1;"
                     :: "r"(mbar_addr), "r"((uint32_t)(SROWS * W * 4))
                     : "memory");
        #pragma unroll
        for (int j = 0; j < SROWS; j++) {
            int yy = y0 - 1 + j;
            yy = (yy < 0) ? 1 : ((yy >= H) ? (2 * H - 2 - yy) : yy);
            const uint32_t daddr =
                (uint32_t)__cvta_generic_to_shared(&srows[j][0]);
            const float* src = img + (size_t)yy * W;
            asm volatile(
                "cp.async.bulk.shared::cta.global.mbarrier::complete_tx::bytes "
                "[%0], [%1], %2, [%3];"
                :: "r"(daddr), "l"(src), "n"(W * 4), "r"(mbar_addr)
                : "memory");
        }
    }

    // All threads wait for the staged tile (phase parity 0).
    asm volatile(
        "{\n\t"
        ".reg .pred P;\n\t"
        "WAIT_%=:\n\t"
        "mbarrier.try_wait.parity.acquire.cta.shared::cta.b64 P, [%0], 0, 0x989680;\n\t"
        "@P bra.uni DONE_%=;\n\t"
        "bra.uni WAIT_%=;\n\t"
        "DONE_%=:\n\t"
        "}"
        :: "r"(mbar_addr) : "memory");

    // Rolling-register walk down the strip: 1 LDS.128 + 2 scalar LDS per row.
    float4 a = *(const float4*)&srows[0][4 * t];   // row above
    float4 b = *(const float4*)&srows[1][4 * t];   // center row

    #pragma unroll
    for (int i = 0; i < ROWS; i++) {
        const float4 d = *(const float4*)&srows[i + 2][4 * t];

        // Horizontal halo straight from smem; image-edge reflection uses the
        // in-register neighbors (left of col0 reflects to col1 = b.y, etc).
        const float left  = (t == 0)      ? b.y : srows[i + 1][4 * t - 1];
        const float right = (t == W4 - 1) ? b.z : srows[i + 1][4 * t + 4];

        float4 g;
        g.x = a.x + d.x + left + b.y  - 4.0f * b.x;
        g.y = a.y + d.y + b.x  + b.z  - 4.0f * b.y;
        g.z = a.z + d.z + b.y  + b.w  - 4.0f * b.z;
        g.w = a.w + d.w + b.z  + right - 4.0f * b.w;

        float4 r;
        float gg, co, v;
        gg = g.x; co = __expf(-gg * gg * 100.0f);
        v = fmaf(gg * co, 0.15f, b.x); r.x = fminf(fmaxf(v, 0.0f), 1.0f);
        gg = g.y; co = __expf(-gg * gg * 100.0f);
        v = fmaf(gg * co, 0.15f, b.y); r.y = fminf(fmaxf(v, 0.0f), 1.0f);
        gg = g.z; co = __expf(-gg * gg * 100.0f);
        v = fmaf(gg * co, 0.15f, b.z); r.z = fminf(fmaxf(v, 0.0f), 1.0f);
        gg = g.w; co = __expf(-gg * gg * 100.0f);
        v = fmaf(gg * co, 0.15f, b.w); r.w = fminf(fmaxf(v, 0.0f), 1.0f);

        stcs4((float4*)(o + (size_t)(y0 + i) * W) + t, r);

        a = b; b = d;
    }
}

extern "C" void kernel_launch(void* const* d_in, const int* in_sizes, int n_in,
                              void* d_out, int out_size) {
    const float* image = (const float*)d_in[0];
    // d_in[1] is the fixed 3x3 Laplace kernel; hardcoded in pm_kernel.
    float* out = (float*)d_out;

    const int n_images = in_sizes[0] / (W * H);   // 64
    dim3 grid(H / ROWS, n_images);
    pm_kernel<<<grid, 256>>>(image, out);
}

// round 10
// speedup vs baseline: 1.0206x; 1.0206x over previous
#include <cuda_runtime.h>
#include <cstdint>

// Perona-Malik single diffusion step — TMA bulk-load staging (4 output rows,
// 6 staged rows = 24KB) with a SPLIT mbarrier (rows 0-3 / rows 4-5) so
// compute starts before the full tile lands. Rolling-register compute from
// smem, direct streaming stores.
// out = clamp(image + g * exp(-g^2/K^2) * dt, 0, 1)
// g   = 5-point Laplacian with ReflectionPad2d(1); K=0.1 (1/K^2=100), dt=0.15

#define W 1024
#define H 1024
#define W4 (W / 4)
#define ROWS 4
#define SROWS (ROWS + 2)

__device__ __forceinline__ void stcs4(float4* p, float4 v) {
    asm volatile("st.global.cs.v4.f32 [%0], {%1,%2,%3,%4};"
                 :: "l"(p), "f"(v.x), "f"(v.y), "f"(v.z), "f"(v.w) : "memory");
}

__device__ __forceinline__ void mbar_wait0(uint32_t addr) {
    asm volatile(
        "{\n\t"
        ".reg .pred P;\n\t"
        "WAIT_%=:\n\t"
        "mbarrier.try_wait.parity.acquire.cta.shared::cta.b64 P, [%0], 0, 0x989680;\n\t"
        "@P bra.uni DONE_%=;\n\t"
        "bra.uni WAIT_%=;\n\t"
        "DONE_%=:\n\t"
        "}"
        :: "r"(addr) : "memory");
}

__global__ __launch_bounds__(256, 8)
void pm_kernel(const float* __restrict__ in, float* __restrict__ out) {
    __shared__ __align__(16) float srows[SROWS][W];   // 24 KB
    __shared__ __align__(8) unsigned long long mbar[2];

    const int y0 = blockIdx.x * ROWS;      // first output row of this block
    const int n  = blockIdx.y;             // image index
    const int t  = threadIdx.x;            // float4 column 0..255

    const float* img = in  + (size_t)n * (W * H);
    float*       o   = out + (size_t)n * (W * H);

    const uint32_t mb0 = (uint32_t)__cvta_generic_to_shared(&mbar[0]);
    const uint32_t mb1 = (uint32_t)__cvta_generic_to_shared(&mbar[1]);

    if (t == 0) {
        asm volatile("mbarrier.init.shared.b64 [%0], 1;" :: "r"(mb0));
        asm volatile("mbarrier.init.shared.b64 [%0], 1;" :: "r"(mb1));
    }
    __syncthreads();

    // Elected thread issues all 6 bulk row copies up front.
    // srows 0-3 complete on bar0 (enough for outputs 0,1);
    // srows 4-5 complete on bar1 (completes outputs 2,3).
    if (t == 0) {
        asm volatile("mbarrier.arrive.expect_tx.shared.b64 _, [%0], %1;"
                     :: "r"(mb0), "r"((uint32_t)(4 * W * 4)) : "memory");
        asm volatile("mbarrier.arrive.expect_tx.shared.b64 _, [%0], %1;"
                     :: "r"(mb1), "r"((uint32_t)(2 * W * 4)) : "memory");
        #pragma unroll
        for (int j = 0; j < SROWS; j++) {
            int yy = y0 - 1 + j;
            yy = (yy < 0) ? 1 : ((yy >= H) ? (2 * H - 2 - yy) : yy);
            const uint32_t daddr =
                (uint32_t)__cvta_generic_to_shared(&srows[j][0]);
            const float* src = img + (size_t)yy * W;
            const uint32_t bar = (j < 4) ? mb0 : mb1;
            asm volatile(
                "cp.async.bulk.shared::cta.global.mbarrier::complete_tx::bytes "
                "[%0], [%1], %2, [%3];"
                :: "r"(daddr), "l"(src), "n"(W * 4), "r"(bar)
                : "memory");
        }
    }

    // Wait for the first 4 staged rows, start computing immediately.
    mbar_wait0(mb0);

    float4 a = *(const float4*)&srows[0][4 * t];   // row above
    float4 b = *(const float4*)&srows[1][4 * t];   // center row

    #pragma unroll
    for (int i = 0; i < ROWS; i++) {
        if (i == 2) mbar_wait0(mb1);   // srows 4,5 needed from here on

        const float4 d = *(const float4*)&srows[i + 2][4 * t];

        // Horizontal halo straight from smem; image-edge reflection uses the
        // in-register neighbors (left of col0 reflects to col1 = b.y, etc).
        const float left  = (t == 0)      ? b.y : srows[i + 1][4 * t - 1];
        const float right = (t == W4 - 1) ? b.z : srows[i + 1][4 * t + 4];

        float4 g;
        g.x = a.x + d.x + left + b.y  - 4.0f * b.x;
        g.y = a.y + d.y + b.x  + b.z  - 4.0f * b.y;
        g.z = a.z + d.z + b.y  + b.w  - 4.0f * b.z;
        g.w = a.w + d.w + b.z  + right - 4.0f * b.w;

        float4 r;
        float gg, co, v;
        gg = g.x; co = __expf(-gg * gg * 100.0f);
        v = fmaf(gg * co, 0.15f, b.x); r.x = fminf(fmaxf(v, 0.0f), 1.0f);
        gg = g.y; co = __expf(-gg * gg * 100.0f);
        v = fmaf(gg * co, 0.15f, b.y); r.y = fminf(fmaxf(v, 0.0f), 1.0f);
        gg = g.z; co = __expf(-gg * gg * 100.0f);
        v = fmaf(gg * co, 0.15f, b.z); r.z = fminf(fmaxf(v, 0.0f), 1.0f);
        gg = g.w; co = __expf(-gg * gg * 100.0f);
        v = fmaf(gg * co, 0.15f, b.w); r.w = fminf(fmaxf(v, 0.0f), 1.0f);

        stcs4((float4*)(o + (size_t)(y0 + i) * W) + t, r);

        a = b; b = d;
    }
}

extern "C" void kernel_launch(void* const* d_in, const int* in_sizes, int n_in,
                              void* d_out, int out_size) {
    const float* image = (const float*)d_in[0];
    // d_in[1] is the fixed 3x3 Laplace kernel; hardcoded in pm_kernel.
    float* out = (float*)d_out;

    const int n_images = in_sizes[0] / (W * H);   // 64
    dim3 grid(H / ROWS, n_images);
    pm_kernel<<<grid, 256>>>(image, out);
}